// round 5
// baseline (speedup 1.0000x reference)
#include <cuda_runtime.h>
#include <cstdint>

#define BB 2
#define SS 1024
#define CC 1024
#define HH 16

// scratch (device globals: no allocation allowed)
__device__ float g_mu[BB*SS];
__device__ float g_rs[BB*SS];
__device__ float g_p[BB*SS*240];     // projection result, row-major [token][240]
__device__ float g_Q[BB*HH*SS*8];    // [qr'*3, qd'*3, code, pad]
__device__ float g_K[BB*HH*SS*12];   // [kr*3, pad][kd'*3, code][v*3, pad]
__device__ float g_att[BB*SS*48];    // (b,s, h*3+i) pre-output

__device__ __forceinline__ float warp_sum(float v){
  #pragma unroll
  for (int o = 16; o > 0; o >>= 1) v += __shfl_xor_sync(0xffffffffu, v, o);
  return v;
}

__device__ __forceinline__ float fast_sqrt(float x){
  float r; asm("sqrt.approx.f32 %0, %1;" : "=f"(r) : "f"(x)); return r;
}
__device__ __forceinline__ float fast_ex2(float x){
  float r; asm("ex2.approx.f32 %0, %1;" : "=f"(r) : "f"(x)); return r;
}
__device__ __forceinline__ float softplus(float x){
  return x > 20.f ? x : log1pf(__expf(x));
}

// ---------------------------------------------------------------------------
// k1a: per-row layernorm stats. one warp per row.
// ---------------------------------------------------------------------------
__global__ __launch_bounds__(256) void k1a_stats(const float* __restrict__ s)
{
  const int lane = threadIdx.x & 31;
  const int row  = blockIdx.x*8 + (threadIdx.x >> 5);
  const float* sr = s + (size_t)row * CC;
  float sum = 0.f, sq = 0.f;
  #pragma unroll
  for (int i = 0; i < 8; i++) {
    float4 v = *(const float4*)(sr + i*128 + lane*4);
    sum += v.x + v.y + v.z + v.w;
    sq  += v.x*v.x + v.y*v.y + v.z*v.z + v.w*v.w;
  }
  sum = warp_sum(sum); sq = warp_sum(sq);
  if (lane == 0) {
    float mean = sum * (1.f/CC);
    float var  = sq * (1.f/CC) - mean*mean;
    g_mu[row] = mean;
    g_rs[row] = rsqrtf(var + 1e-5f);
  }
}

// ---------------------------------------------------------------------------
// k1b: p[r][d] = sum_c ns[r][c]*W[d][c].  BM=64, BN=64 (240 padded), BK=32.
// 256 threads, 4x4 micro-tile. smem [k][m]/[k][n] stride 68.
// ---------------------------------------------------------------------------
#define ST 68
__global__ __launch_bounds__(256) void k1b_gemm(
    const float* __restrict__ s, const float* __restrict__ ln_w,
    const float* __restrict__ w_proj)
{
  __shared__ __align__(16) float As[32*ST];
  __shared__ __align__(16) float Bs[32*ST];
  __shared__ float mu_s[64], rs_s[64];

  const int t  = threadIdx.x;
  const int bx = blockIdx.x;           // n-tile 0..3
  const int by = blockIdx.y;           // m-tile 0..31
  const int rfill = t >> 3;            // 0..31
  const int c4    = (t & 7) * 4;       // 0..28
  const int tx = t & 15, ty = t >> 4;

  if (t < 64) { mu_s[t] = g_mu[by*64 + t]; rs_s[t] = g_rs[by*64 + t]; }

  float acc[4][4];
  #pragma unroll
  for (int i = 0; i < 4; i++)
    #pragma unroll
    for (int j = 0; j < 4; j++) acc[i][j] = 0.f;

  __syncthreads();

  for (int kt = 0; kt < 32; kt++) {
    const int cg = kt*32 + c4;
    float4 lw = *(const float4*)(ln_w + cg);
    #pragma unroll
    for (int ph = 0; ph < 2; ph++) {
      int r = rfill + ph*32;
      // A: normalized s
      float4 sv = *(const float4*)(s + (size_t)(by*64 + r)*CC + cg);
      float m_ = mu_s[r], rr = rs_s[r];
      As[(c4+0)*ST + r] = (sv.x - m_)*rr*lw.x;
      As[(c4+1)*ST + r] = (sv.y - m_)*rr*lw.y;
      As[(c4+2)*ST + r] = (sv.z - m_)*rr*lw.z;
      As[(c4+3)*ST + r] = (sv.w - m_)*rr*lw.w;
      // B: w_proj rows (padded with zeros for d >= 240)
      int dg = bx*64 + r;
      float4 wv = make_float4(0.f,0.f,0.f,0.f);
      if (dg < 240) wv = *(const float4*)(w_proj + (size_t)dg*CC + cg);
      Bs[(c4+0)*ST + r] = wv.x;
      Bs[(c4+1)*ST + r] = wv.y;
      Bs[(c4+2)*ST + r] = wv.z;
      Bs[(c4+3)*ST + r] = wv.w;
    }
    __syncthreads();
    #pragma unroll
    for (int k = 0; k < 32; k++) {
      float4 a = *(const float4*)&As[k*ST + ty*4];
      float4 b = *(const float4*)&Bs[k*ST + tx*4];
      float av[4] = {a.x, a.y, a.z, a.w};
      float bv[4] = {b.x, b.y, b.z, b.w};
      #pragma unroll
      for (int i = 0; i < 4; i++)
        #pragma unroll
        for (int j = 0; j < 4; j++) acc[i][j] += av[i]*bv[j];
    }
    __syncthreads();
  }

  const int d = bx*64 + tx*4;
  if (d < 240) {
    #pragma unroll
    for (int i = 0; i < 4; i++) {
      int row = by*64 + ty*4 + i;
      float4 res = make_float4(acc[i][0], acc[i][1], acc[i][2], acc[i][3]);
      *(float4*)&g_p[(size_t)row*240 + d] = res;
    }
  }
}

// ---------------------------------------------------------------------------
// k1c: rotate 3-vectors, fold all softmax scales, scatter to Q/K layout.
// one thread per (token, vec v in [0,80)).
// ---------------------------------------------------------------------------
__global__ __launch_bounds__(256) void k1c_scatter(
    const float* __restrict__ rot, const float* __restrict__ trans,
    const float* __restrict__ dist_scale, const float* __restrict__ rot_scale,
    const int* __restrict__ amask,
    const int* __restrict__ seq_id, const int* __restrict__ chain_id)
{
  const float SCL = 1.4426950408889634f / 1.7320508075688772f; // invln2/sqrt3
  int idx = blockIdx.x*256 + threadIdx.x;      // 2048*80 total
  int token = idx / 80;
  int v = idx - token*80;
  int b = token >> 10, sl = token & 1023;

  const float* P = g_p + (size_t)token*240 + v*3;
  float x = P[0], y = P[1], z = P[2];
  const float* R = rot + (size_t)token*9;
  float o0 = R[0]*x + R[1]*y + R[2]*z;
  float o1 = R[3]*x + R[4]*y + R[5]*z;
  float o2 = R[6]*x + R[7]*y + R[8]*z;

  if (v < 16) {                 // Q rot, scaled by rw'
    int h = v;
    float rw = softplus(rot_scale[h]) * SCL;
    float* q = &g_Q[((size_t)((b*HH + h)*SS) + sl)*8];
    q[0] = o0*rw; q[1] = o1*rw; q[2] = o2*rw;
  } else if (v < 32) {          // K rot, unscaled
    int h = v - 16;
    float* k = &g_K[((size_t)((b*HH + h)*SS) + sl)*12];
    k[0] = o0; k[1] = o1; k[2] = o2;
  } else if (v < 48) {          // V
    int h = v - 32;
    float* k = &g_K[((size_t)((b*HH + h)*SS) + sl)*12];
    k[8] = o0; k[9] = o1; k[10] = o2;
  } else if (v < 64) {          // Q dist: +trans, scaled by dw'
    int h = v - 48;
    float dw = softplus(dist_scale[h]) * SCL;
    float* q = &g_Q[((size_t)((b*HH + h)*SS) + sl)*8];
    q[3] = (o0 + trans[token*3+0])*dw;
    q[4] = (o1 + trans[token*3+1])*dw;
    q[5] = (o2 + trans[token*3+2])*dw;
    int code = (chain_id[token] << 16) | (seq_id[token] & 0xFFFF);
    q[6] = __int_as_float(code);
  } else {                      // K dist: +trans, scaled by dw'; code w/ mask
    int h = v - 64;
    float dw = softplus(dist_scale[h]) * SCL;
    float* k = &g_K[((size_t)((b*HH + h)*SS) + sl)*12];
    k[4] = (o0 + trans[token*3+0])*dw;
    k[5] = (o1 + trans[token*3+1])*dw;
    k[6] = (o2 + trans[token*3+2])*dw;
    int code = (chain_id[token] << 16) | (seq_id[token] & 0xFFFF);
    k[7] = __int_as_float(amask[token] != 0 ? code : -1);
  }
}

// ---------------------------------------------------------------------------
// k2: geometric attention in base-2 domain. block = (b,h,128-q tile),
// warp = 16 q rows as two 8-row register tiles; lane strides over k.
// ---------------------------------------------------------------------------
__global__ __launch_bounds__(256) void k2_attn(
    const float* __restrict__ rot, const int* __restrict__ amask)
{
  const float INVLN2 = 1.4426950408889634f;
  const int qt   = blockIdx.x & 7;
  const int h    = (blockIdx.x >> 3) & 15;
  const int b    = blockIdx.x >> 7;
  const int lane = threadIdx.x & 31;
  const int w    = threadIdx.x >> 5;

  const float* Kb = g_K + (size_t)((b*HH + h)*SS)*12;
  const float* Qb = g_Q + (size_t)((b*HH + h)*SS)*8;

  const int qwarpbase = qt*128 + w*16;
  for (int chunk = 0; chunk < 2; chunk++) {
    const int q0 = qwarpbase + chunk*8;
    float qr0[8], qr1[8], qr2[8], qd0[8], qd1[8], qd2[8];
    int qcode[8], qch[8];
    #pragma unroll
    for (int r = 0; r < 8; r++) {
      const float* qp = Qb + (size_t)(q0 + r)*8;
      float4 a  = *(const float4*)qp;
      float4 bq = *(const float4*)(qp + 4);
      qr0[r] = a.x;  qr1[r] = a.y;  qr2[r] = a.z;
      qd0[r] = a.w;  qd1[r] = bq.x; qd2[r] = bq.y;
      qcode[r] = __float_as_int(bq.z);
      qch[r]   = qcode[r] >> 16;
    }
    float l[8], a0[8], a1[8], a2[8];
    #pragma unroll
    for (int r = 0; r < 8; r++) { l[r]=0.f; a0[r]=0.f; a1[r]=0.f; a2[r]=0.f; }

    for (int ki = 0; ki < 32; ki++) {
      const int kk = ki*32 + lane;
      const float* kp = Kb + (size_t)kk*12;
      float4 kA = *(const float4*)kp;          // kr0 kr1 kr2 _
      float4 kB = *(const float4*)(kp + 4);    // kd0 kd1 kd2 code
      float4 kC = *(const float4*)(kp + 8);    // v0 v1 v2 _
      int kcode  = __float_as_int(kB.w);
      int kchain = kcode >> 16;
      #pragma unroll
      for (int r = 0; r < 8; r++) {
        float rt  = qr0[r]*kA.x + qr1[r]*kA.y + qr2[r]*kA.z;
        float ddx = qd0[r]-kB.x, ddy = qd1[r]-kB.y, ddz = qd2[r]-kB.z;
        float d2  = ddx*ddx + ddy*ddy + ddz*ddz;
        float bias = (kcode == qcode[r]) ? INVLN2
                   : (kchain == qch[r] ? 0.0f : -1e30f);
        float sc = rt - fast_sqrt(d2) + bias;
        float p = fast_ex2(sc);
        l[r]  += p;
        a0[r] += p*kC.x; a1[r] += p*kC.y; a2[r] += p*kC.z;
      }
    }
    #pragma unroll
    for (int r = 0; r < 8; r++) {
      float L  = warp_sum(l[r]);
      float A0 = warp_sum(a0[r]);
      float A1 = warp_sum(a1[r]);
      float A2 = warp_sum(a2[r]);
      if (lane == r) {
        int q = q0 + r;
        float inv = 1.f / L;
        float o0 = A0*inv, o1 = A1*inv, o2 = A2*inv;
        int row = b*SS + q;
        const float* R = rot + (size_t)row*9;
        float u0 = R[0]*o0 + R[3]*o1 + R[6]*o2;
        float u1 = R[1]*o0 + R[4]*o1 + R[7]*o2;
        float u2 = R[2]*o0 + R[5]*o1 + R[8]*o2;
        float mk = (amask[row] != 0) ? 1.f : 0.f;
        float* op = g_att + (size_t)row*48 + h*3;
        op[0] = u0*mk; op[1] = u1*mk; op[2] = u2*mk;
      }
    }
  }
}

// ---------------------------------------------------------------------------
// k3: out[b,s,c] = sum_d att[b,s,d] * w_out[c,d]
// ---------------------------------------------------------------------------
__global__ __launch_bounds__(256) void k3_out(
    const float* __restrict__ w_out, float* __restrict__ out)
{
  __shared__ float w_s[48*64];    // [d][c]
  __shared__ float a_s[48*128];   // [d][r]
  const int tid = threadIdx.x;
  const int ct = blockIdx.x & 15, st = blockIdx.x >> 4;
  const int cb = ct*64, sb = st*128;

  for (int idx = tid; idx < 64*48; idx += 256) {
    int c = idx/48, d = idx - c*48;
    w_s[d*64 + c] = w_out[(size_t)(cb + c)*48 + d];
  }
  for (int idx = tid; idx < 128*48; idx += 256) {
    int r = idx/48, d = idx - r*48;
    a_s[d*128 + r] = g_att[(size_t)(sb + r)*48 + d];
  }
  __syncthreads();

  const int tx = tid & 15, ty = tid >> 4;
  float acc[8][4];
  #pragma unroll
  for (int i = 0; i < 8; i++)
    #pragma unroll
    for (int j = 0; j < 4; j++) acc[i][j] = 0.f;

  #pragma unroll 4
  for (int d = 0; d < 48; d++) {
    float4 wv = *(const float4*)&w_s[d*64 + tx*4];
    float4 aA = *(const float4*)&a_s[d*128 + ty*8];
    float4 aB = *(const float4*)&a_s[d*128 + ty*8 + 4];
    float av[8] = {aA.x, aA.y, aA.z, aA.w, aB.x, aB.y, aB.z, aB.w};
    #pragma unroll
    for (int i = 0; i < 8; i++) {
      acc[i][0] += av[i]*wv.x;
      acc[i][1] += av[i]*wv.y;
      acc[i][2] += av[i]*wv.z;
      acc[i][3] += av[i]*wv.w;
    }
  }
  #pragma unroll
  for (int i = 0; i < 8; i++) {
    float4 res = make_float4(acc[i][0], acc[i][1], acc[i][2], acc[i][3]);
    *(float4*)&out[(size_t)(sb + ty*8 + i)*1024 + cb + tx*4] = res;
  }
}

// ---------------------------------------------------------------------------
extern "C" void kernel_launch(void* const* d_in, const int* in_sizes, int n_in,
                              void* d_out, int out_size)
{
  const float* s          = (const float*)d_in[0];
  const float* rot        = (const float*)d_in[1];
  const float* trans      = (const float*)d_in[2];
  const float* ln_w       = (const float*)d_in[3];
  const float* w_proj     = (const float*)d_in[4];
  const float* w_out      = (const float*)d_in[5];
  const float* dist_scale = (const float*)d_in[6];
  const float* rot_scale  = (const float*)d_in[7];
  const int* am           = (const int*)d_in[8];
  const int* seq_id       = (const int*)d_in[9];
  const int* chain_id     = (const int*)d_in[10];
  float* out = (float*)d_out;

  k1a_stats  <<<256, 256>>>(s);
  k1b_gemm   <<<dim3(4,32), 256>>>(s, ln_w, w_proj);
  k1c_scatter<<<640, 256>>>(rot, trans, dist_scale, rot_scale, am, seq_id, chain_id);
  k2_attn    <<<256, 256>>>(rot, am);
  k3_out     <<<256, 256>>>(w_out, out);
}

// round 8
// speedup vs baseline: 1.4171x; 1.4171x over previous
#include <cuda_runtime.h>
#include <cstdint>

#define BB 2
#define SS 1024
#define CC 1024
#define HH 16

// scratch (device globals: no allocation allowed)
__device__ float g_mu[BB*SS];
__device__ float g_rs[BB*SS];
__device__ float g_p[BB*SS*240];            // projection result [token][240]
// SoA float4 streams, indexed [(b*HH+h)*SS + k]
__device__ float4 g_QA[BB*HH*SS];           // {qr0*rw, qr1*rw, qr2*rw, code}
__device__ float4 g_QB[BB*HH*SS];           // {qd0*dw, qd1*dw, qd2*dw, 0}
__device__ float4 g_KA[BB*HH*SS];           // {kr0, kr1, kr2, codeMasked}
__device__ float4 g_KB[BB*HH*SS];           // {kd0*dw, kd1*dw, kd2*dw, 0}
__device__ float4 g_KV[BB*HH*SS];           // {v0, v1, v2, 0}
__device__ float g_att[BB*SS*48];           // (b,s, h*3+i) pre-output

__device__ __forceinline__ float warp_sum(float v){
  #pragma unroll
  for (int o = 16; o > 0; o >>= 1) v += __shfl_xor_sync(0xffffffffu, v, o);
  return v;
}
__device__ __forceinline__ float fast_sqrt(float x){
  float r; asm("sqrt.approx.f32 %0, %1;" : "=f"(r) : "f"(x)); return r;
}
__device__ __forceinline__ float fast_ex2(float x){
  float r; asm("ex2.approx.f32 %0, %1;" : "=f"(r) : "f"(x)); return r;
}
__device__ __forceinline__ float softplus(float x){
  return x > 20.f ? x : log1pf(__expf(x));
}

// ---------------------------------------------------------------------------
// k1a: per-row layernorm stats. one warp per row.
// ---------------------------------------------------------------------------
__global__ __launch_bounds__(256) void k1a_stats(const float* __restrict__ s)
{
  const int lane = threadIdx.x & 31;
  const int row  = blockIdx.x*8 + (threadIdx.x >> 5);
  const float* sr = s + (size_t)row * CC;
  float sum = 0.f, sq = 0.f;
  #pragma unroll
  for (int i = 0; i < 8; i++) {
    float4 v = *(const float4*)(sr + i*128 + lane*4);
    sum += v.x + v.y + v.z + v.w;
    sq  += v.x*v.x + v.y*v.y + v.z*v.z + v.w*v.w;
  }
  sum = warp_sum(sum); sq = warp_sum(sq);
  if (lane == 0) {
    float mean = sum * (1.f/CC);
    float var  = sq * (1.f/CC) - mean*mean;
    g_mu[row] = mean;
    g_rs[row] = rsqrtf(var + 1e-5f);
  }
}

// ---------------------------------------------------------------------------
// k1b: p[r][d] = sum_c ns[r][c]*W[d][c].  BM=64, BN=64 (240 padded), BK=32.
// ---------------------------------------------------------------------------
#define ST 68
__global__ __launch_bounds__(256) void k1b_gemm(
    const float* __restrict__ s, const float* __restrict__ ln_w,
    const float* __restrict__ w_proj)
{
  __shared__ __align__(16) float As[32*ST];
  __shared__ __align__(16) float Bs[32*ST];
  __shared__ float mu_s[64], rs_s[64];

  const int t  = threadIdx.x;
  const int bx = blockIdx.x;           // n-tile 0..3
  const int by = blockIdx.y;           // m-tile 0..31
  const int rfill = t >> 3;            // 0..31
  const int c4    = (t & 7) * 4;       // 0..28
  const int tx = t & 15, ty = t >> 4;

  if (t < 64) { mu_s[t] = g_mu[by*64 + t]; rs_s[t] = g_rs[by*64 + t]; }

  float acc[4][4];
  #pragma unroll
  for (int i = 0; i < 4; i++)
    #pragma unroll
    for (int j = 0; j < 4; j++) acc[i][j] = 0.f;

  __syncthreads();

  for (int kt = 0; kt < 32; kt++) {
    const int cg = kt*32 + c4;
    float4 lw = *(const float4*)(ln_w + cg);
    #pragma unroll
    for (int ph = 0; ph < 2; ph++) {
      int r = rfill + ph*32;
      float4 sv = *(const float4*)(s + (size_t)(by*64 + r)*CC + cg);
      float m_ = mu_s[r], rr = rs_s[r];
      As[(c4+0)*ST + r] = (sv.x - m_)*rr*lw.x;
      As[(c4+1)*ST + r] = (sv.y - m_)*rr*lw.y;
      As[(c4+2)*ST + r] = (sv.z - m_)*rr*lw.z;
      As[(c4+3)*ST + r] = (sv.w - m_)*rr*lw.w;
      int dg = bx*64 + r;
      float4 wv = make_float4(0.f,0.f,0.f,0.f);
      if (dg < 240) wv = *(const float4*)(w_proj + (size_t)dg*CC + cg);
      Bs[(c4+0)*ST + r] = wv.x;
      Bs[(c4+1)*ST + r] = wv.y;
      Bs[(c4+2)*ST + r] = wv.z;
      Bs[(c4+3)*ST + r] = wv.w;
    }
    __syncthreads();
    #pragma unroll
    for (int k = 0; k < 32; k++) {
      float4 a = *(const float4*)&As[k*ST + ty*4];
      float4 b = *(const float4*)&Bs[k*ST + tx*4];
      float av[4] = {a.x, a.y, a.z, a.w};
      float bv[4] = {b.x, b.y, b.z, b.w};
      #pragma unroll
      for (int i = 0; i < 4; i++)
        #pragma unroll
        for (int j = 0; j < 4; j++) acc[i][j] += av[i]*bv[j];
    }
    __syncthreads();
  }

  const int d = bx*64 + tx*4;
  if (d < 240) {
    #pragma unroll
    for (int i = 0; i < 4; i++) {
      int row = by*64 + ty*4 + i;
      float4 res = make_float4(acc[i][0], acc[i][1], acc[i][2], acc[i][3]);
      *(float4*)&g_p[(size_t)row*240 + d] = res;
    }
  }
}

// ---------------------------------------------------------------------------
// k1c: rotate 3-vectors, fold all softmax scales, scatter to SoA Q/K layout.
// one thread per (token, vec v in [0,80)); each does one float4 store.
// ---------------------------------------------------------------------------
__global__ __launch_bounds__(256) void k1c_scatter(
    const float* __restrict__ rot, const float* __restrict__ trans,
    const float* __restrict__ dist_scale, const float* __restrict__ rot_scale,
    const int* __restrict__ amask,
    const int* __restrict__ seq_id, const int* __restrict__ chain_id)
{
  const float SCL = 1.4426950408889634f / 1.7320508075688772f; // invln2/sqrt3
  int idx = blockIdx.x*256 + threadIdx.x;      // 2048*80 total
  int token = idx / 80;
  int v = idx - token*80;
  int b = token >> 10, sl = token & 1023;

  const float* P = g_p + (size_t)token*240 + v*3;
  float x = P[0], y = P[1], z = P[2];
  const float* R = rot + (size_t)token*9;
  float o0 = R[0]*x + R[1]*y + R[2]*z;
  float o1 = R[3]*x + R[4]*y + R[5]*z;
  float o2 = R[6]*x + R[7]*y + R[8]*z;

  if (v < 16) {                 // Q rot, scaled by rw'; carries code
    int h = v;
    float rw = softplus(rot_scale[h]) * SCL;
    int code = (chain_id[token] << 16) | (seq_id[token] & 0xFFFF);
    g_QA[(size_t)((b*HH + h)*SS) + sl] =
        make_float4(o0*rw, o1*rw, o2*rw, __int_as_float(code));
  } else if (v < 32) {          // K rot, unscaled; carries masked code
    int h = v - 16;
    int code = (chain_id[token] << 16) | (seq_id[token] & 0xFFFF);
    int mc = (amask[token] != 0) ? code : -1;
    g_KA[(size_t)((b*HH + h)*SS) + sl] =
        make_float4(o0, o1, o2, __int_as_float(mc));
  } else if (v < 48) {          // V
    int h = v - 32;
    g_KV[(size_t)((b*HH + h)*SS) + sl] = make_float4(o0, o1, o2, 0.f);
  } else if (v < 64) {          // Q dist: +trans, scaled by dw'
    int h = v - 48;
    float dw = softplus(dist_scale[h]) * SCL;
    g_QB[(size_t)((b*HH + h)*SS) + sl] =
        make_float4((o0 + trans[token*3+0])*dw,
                    (o1 + trans[token*3+1])*dw,
                    (o2 + trans[token*3+2])*dw, 0.f);
  } else {                      // K dist: +trans, scaled by dw'
    int h = v - 64;
    float dw = softplus(dist_scale[h]) * SCL;
    g_KB[(size_t)((b*HH + h)*SS) + sl] =
        make_float4((o0 + trans[token*3+0])*dw,
                    (o1 + trans[token*3+1])*dw,
                    (o2 + trans[token*3+2])*dw, 0.f);
  }
}

// ---------------------------------------------------------------------------
// k2: geometric attention, base-2 domain. block = (b, h, 64-q tile),
// 128 threads; warp = 16 q rows in four 4-row register tiles; lanes over k.
// ---------------------------------------------------------------------------
__global__ __launch_bounds__(128) void k2_attn(
    const float* __restrict__ rot, const int* __restrict__ amask)
{
  const float INVLN2 = 1.4426950408889634f;
  const int qt   = blockIdx.x & 15;          // 16 tiles of 64 q rows
  const int h    = (blockIdx.x >> 4) & 15;
  const int b    = blockIdx.x >> 8;
  const int lane = threadIdx.x & 31;
  const int w    = threadIdx.x >> 5;         // 0..3

  const size_t base = (size_t)(b*HH + h)*SS;
  const float4* KA = g_KA + base;
  const float4* KB = g_KB + base;
  const float4* KV = g_KV + base;
  const float4* QA = g_QA + base;
  const float4* QB = g_QB + base;

  const int qwarp = qt*64 + w*16;
  #pragma unroll 1
  for (int chunk = 0; chunk < 4; chunk++) {
    const int q0 = qwarp + chunk*4;
    float qr0[4], qr1[4], qr2[4], qd0[4], qd1[4], qd2[4];
    int qcode[4], qch[4];
    #pragma unroll
    for (int r = 0; r < 4; r++) {
      float4 a  = QA[q0 + r];
      float4 dq = QB[q0 + r];
      qr0[r] = a.x;  qr1[r] = a.y;  qr2[r] = a.z;
      qcode[r] = __float_as_int(a.w);
      qch[r]   = qcode[r] >> 16;
      qd0[r] = dq.x; qd1[r] = dq.y; qd2[r] = dq.z;
    }
    float l[4], a0[4], a1[4], a2[4];
    #pragma unroll
    for (int r = 0; r < 4; r++) { l[r]=0.f; a0[r]=0.f; a1[r]=0.f; a2[r]=0.f; }

    #pragma unroll 2
    for (int ki = 0; ki < 32; ki++) {
      const int kk = ki*32 + lane;
      float4 ka = KA[kk];
      float4 kb = KB[kk];
      float4 kv = KV[kk];
      int kcode  = __float_as_int(ka.w);
      int kchain = kcode >> 16;
      #pragma unroll
      for (int r = 0; r < 4; r++) {
        float rt  = qr0[r]*ka.x + qr1[r]*ka.y + qr2[r]*ka.z;
        float ddx = qd0[r]-kb.x, ddy = qd1[r]-kb.y, ddz = qd2[r]-kb.z;
        float d2  = ddx*ddx + ddy*ddy + ddz*ddz;
        float bias = (kcode == qcode[r]) ? INVLN2
                   : (kchain == qch[r] ? 0.0f : -1e30f);
        float sc = rt - fast_sqrt(d2) + bias;
        float p = fast_ex2(sc);
        l[r]  += p;
        a0[r] += p*kv.x; a1[r] += p*kv.y; a2[r] += p*kv.z;
      }
    }
    #pragma unroll
    for (int r = 0; r < 4; r++) {
      float L  = warp_sum(l[r]);
      float A0 = warp_sum(a0[r]);
      float A1 = warp_sum(a1[r]);
      float A2 = warp_sum(a2[r]);
      if (lane == r) {
        int q = q0 + r;
        float inv = 1.f / L;
        float o0 = A0*inv, o1 = A1*inv, o2 = A2*inv;
        int row = b*SS + q;
        const float* R = rot + (size_t)row*9;
        float u0 = R[0]*o0 + R[3]*o1 + R[6]*o2;
        float u1 = R[1]*o0 + R[4]*o1 + R[7]*o2;
        float u2 = R[2]*o0 + R[5]*o1 + R[8]*o2;
        float mk = (amask[row] != 0) ? 1.f : 0.f;
        float* op = g_att + (size_t)row*48 + h*3;
        op[0] = u0*mk; op[1] = u1*mk; op[2] = u2*mk;
      }
    }
  }
}

// ---------------------------------------------------------------------------
// k3: out[b,s,c] = sum_d att[b,s,d] * w_out[c,d]
// ---------------------------------------------------------------------------
__global__ __launch_bounds__(256) void k3_out(
    const float* __restrict__ w_out, float* __restrict__ out)
{
  __shared__ float w_s[48*64];    // [d][c]
  __shared__ float a_s[48*128];   // [d][r]
  const int tid = threadIdx.x;
  const int ct = blockIdx.x & 15, st = blockIdx.x >> 4;
  const int cb = ct*64, sb = st*128;

  for (int idx = tid; idx < 64*48; idx += 256) {
    int c = idx/48, d = idx - c*48;
    w_s[d*64 + c] = w_out[(size_t)(cb + c)*48 + d];
  }
  for (int idx = tid; idx < 128*48; idx += 256) {
    int r = idx/48, d = idx - r*48;
    a_s[d*128 + r] = g_att[(size_t)(sb + r)*48 + d];
  }
  __syncthreads();

  const int tx = tid & 15, ty = tid >> 4;
  float acc[8][4];
  #pragma unroll
  for (int i = 0; i < 8; i++)
    #pragma unroll
    for (int j = 0; j < 4; j++) acc[i][j] = 0.f;

  #pragma unroll 4
  for (int d = 0; d < 48; d++) {
    float4 wv = *(const float4*)&w_s[d*64 + tx*4];
    float4 aA = *(const float4*)&a_s[d*128 + ty*8];
    float4 aB = *(const float4*)&a_s[d*128 + ty*8 + 4];
    float av[8] = {aA.x, aA.y, aA.z, aA.w, aB.x, aB.y, aB.z, aB.w};
    #pragma unroll
    for (int i = 0; i < 8; i++) {
      acc[i][0] += av[i]*wv.x;
      acc[i][1] += av[i]*wv.y;
      acc[i][2] += av[i]*wv.z;
      acc[i][3] += av[i]*wv.w;
    }
  }
  #pragma unroll
  for (int i = 0; i < 8; i++) {
    float4 res = make_float4(acc[i][0], acc[i][1], acc[i][2], acc[i][3]);
    *(float4*)&out[(size_t)(sb + ty*8 + i)*1024 + cb + tx*4] = res;
  }
}

// ---------------------------------------------------------------------------
extern "C" void kernel_launch(void* const* d_in, const int* in_sizes, int n_in,
                              void* d_out, int out_size)
{
  const float* s          = (const float*)d_in[0];
  const float* rot        = (const float*)d_in[1];
  const float* trans      = (const float*)d_in[2];
  const float* ln_w       = (const float*)d_in[3];
  const float* w_proj     = (const float*)d_in[4];
  const float* w_out      = (const float*)d_in[5];
  const float* dist_scale = (const float*)d_in[6];
  const float* rot_scale  = (const float*)d_in[7];
  const int* am           = (const int*)d_in[8];
  const int* seq_id       = (const int*)d_in[9];
  const int* chain_id     = (const int*)d_in[10];
  float* out = (float*)d_out;

  k1a_stats  <<<256, 256>>>(s);
  k1b_gemm   <<<dim3(4,32), 256>>>(s, ln_w, w_proj);
  k1c_scatter<<<640, 256>>>(rot, trans, dist_scale, rot_scale, am, seq_id, chain_id);
  k2_attn    <<<512, 128>>>(rot, am);
  k3_out     <<<256, 256>>>(w_out, out);
}

// round 10
// speedup vs baseline: 1.6824x; 1.1872x over previous
#include <cuda_runtime.h>
#include <cstdint>

#define BB 2
#define SS 1024
#define CC 1024
#define HH 16

// scratch (device globals: no allocation allowed)
__device__ float g_mu[BB*SS];
__device__ float g_rs[BB*SS];
__device__ float g_p[BB*SS*240];            // projection result [token][240]
// SoA float4 streams, indexed [(b*HH+h)*SS + k]
__device__ float4 g_QA[BB*HH*SS];           // {qr0*rw, qr1*rw, qr2*rw, code}
__device__ float4 g_QB[BB*HH*SS];           // {qd0*dw, qd1*dw, qd2*dw, 0}
__device__ float4 g_KA[BB*HH*SS];           // {kr0, kr1, kr2, codeMasked}
__device__ float4 g_KB[BB*HH*SS];           // {kd0*dw, kd1*dw, kd2*dw, 0}
__device__ float4 g_KV[BB*HH*SS];           // {v0, v1, v2, 0}
__device__ float4 g_part0[BB*HH*SS];        // k-half 0 partials {l, a0, a1, a2}
__device__ float4 g_part1[BB*HH*SS];        // k-half 1 partials
__device__ float g_att[BB*SS*48];           // (b,s, h*3+i) pre-output

__device__ __forceinline__ float warp_sum(float v){
  #pragma unroll
  for (int o = 16; o > 0; o >>= 1) v += __shfl_xor_sync(0xffffffffu, v, o);
  return v;
}
__device__ __forceinline__ float fast_sqrt(float x){
  float r; asm("sqrt.approx.f32 %0, %1;" : "=f"(r) : "f"(x)); return r;
}
__device__ __forceinline__ float fast_ex2(float x){
  float r; asm("ex2.approx.f32 %0, %1;" : "=f"(r) : "f"(x)); return r;
}
__device__ __forceinline__ float softplus(float x){
  return x > 20.f ? x : log1pf(__expf(x));
}

// ---------------------------------------------------------------------------
// k1a: per-row layernorm stats. one warp per row.
// ---------------------------------------------------------------------------
__global__ __launch_bounds__(256) void k1a_stats(const float* __restrict__ s)
{
  const int lane = threadIdx.x & 31;
  const int row  = blockIdx.x*8 + (threadIdx.x >> 5);
  const float* sr = s + (size_t)row * CC;
  float sum = 0.f, sq = 0.f;
  #pragma unroll
  for (int i = 0; i < 8; i++) {
    float4 v = *(const float4*)(sr + i*128 + lane*4);
    sum += v.x + v.y + v.z + v.w;
    sq  += v.x*v.x + v.y*v.y + v.z*v.z + v.w*v.w;
  }
  sum = warp_sum(sum); sq = warp_sum(sq);
  if (lane == 0) {
    float mean = sum * (1.f/CC);
    float var  = sq * (1.f/CC) - mean*mean;
    g_mu[row] = mean;
    g_rs[row] = rsqrtf(var + 1e-5f);
  }
}

// ---------------------------------------------------------------------------
// k1b: p[r][d] = sum_c ns[r][c]*W[d][c].  BM=64, BN=64 (240 padded), BK=32.
// ---------------------------------------------------------------------------
#define ST 68
__global__ __launch_bounds__(256) void k1b_gemm(
    const float* __restrict__ s, const float* __restrict__ ln_w,
    const float* __restrict__ w_proj)
{
  __shared__ __align__(16) float As[32*ST];
  __shared__ __align__(16) float Bs[32*ST];
  __shared__ float mu_s[64], rs_s[64];

  const int t  = threadIdx.x;
  const int bx = blockIdx.x;           // n-tile 0..3
  const int by = blockIdx.y;           // m-tile 0..31
  const int rfill = t >> 3;            // 0..31
  const int c4    = (t & 7) * 4;       // 0..28
  const int tx = t & 15, ty = t >> 4;

  if (t < 64) { mu_s[t] = g_mu[by*64 + t]; rs_s[t] = g_rs[by*64 + t]; }

  float acc[4][4];
  #pragma unroll
  for (int i = 0; i < 4; i++)
    #pragma unroll
    for (int j = 0; j < 4; j++) acc[i][j] = 0.f;

  __syncthreads();

  for (int kt = 0; kt < 32; kt++) {
    const int cg = kt*32 + c4;
    float4 lw = *(const float4*)(ln_w + cg);
    #pragma unroll
    for (int ph = 0; ph < 2; ph++) {
      int r = rfill + ph*32;
      float4 sv = *(const float4*)(s + (size_t)(by*64 + r)*CC + cg);
      float m_ = mu_s[r], rr = rs_s[r];
      As[(c4+0)*ST + r] = (sv.x - m_)*rr*lw.x;
      As[(c4+1)*ST + r] = (sv.y - m_)*rr*lw.y;
      As[(c4+2)*ST + r] = (sv.z - m_)*rr*lw.z;
      As[(c4+3)*ST + r] = (sv.w - m_)*rr*lw.w;
      int dg = bx*64 + r;
      float4 wv = make_float4(0.f,0.f,0.f,0.f);
      if (dg < 240) wv = *(const float4*)(w_proj + (size_t)dg*CC + cg);
      Bs[(c4+0)*ST + r] = wv.x;
      Bs[(c4+1)*ST + r] = wv.y;
      Bs[(c4+2)*ST + r] = wv.z;
      Bs[(c4+3)*ST + r] = wv.w;
    }
    __syncthreads();
    #pragma unroll
    for (int k = 0; k < 32; k++) {
      float4 a = *(const float4*)&As[k*ST + ty*4];
      float4 b = *(const float4*)&Bs[k*ST + tx*4];
      float av[4] = {a.x, a.y, a.z, a.w};
      float bv[4] = {b.x, b.y, b.z, b.w};
      #pragma unroll
      for (int i = 0; i < 4; i++)
        #pragma unroll
        for (int j = 0; j < 4; j++) acc[i][j] += av[i]*bv[j];
    }
    __syncthreads();
  }

  const int d = bx*64 + tx*4;
  if (d < 240) {
    #pragma unroll
    for (int i = 0; i < 4; i++) {
      int row = by*64 + ty*4 + i;
      float4 res = make_float4(acc[i][0], acc[i][1], acc[i][2], acc[i][3]);
      *(float4*)&g_p[(size_t)row*240 + d] = res;
    }
  }
}

// ---------------------------------------------------------------------------
// k1c: rotate 3-vectors, fold all softmax scales, scatter to SoA Q/K layout.
// ---------------------------------------------------------------------------
__global__ __launch_bounds__(256) void k1c_scatter(
    const float* __restrict__ rot, const float* __restrict__ trans,
    const float* __restrict__ dist_scale, const float* __restrict__ rot_scale,
    const int* __restrict__ amask,
    const int* __restrict__ seq_id, const int* __restrict__ chain_id)
{
  const float SCL = 1.4426950408889634f / 1.7320508075688772f; // invln2/sqrt3
  int idx = blockIdx.x*256 + threadIdx.x;      // 2048*80 total
  int token = idx / 80;
  int v = idx - token*80;
  int b = token >> 10, sl = token & 1023;

  const float* P = g_p + (size_t)token*240 + v*3;
  float x = P[0], y = P[1], z = P[2];
  const float* R = rot + (size_t)token*9;
  float o0 = R[0]*x + R[1]*y + R[2]*z;
  float o1 = R[3]*x + R[4]*y + R[5]*z;
  float o2 = R[6]*x + R[7]*y + R[8]*z;

  if (v < 16) {                 // Q rot, scaled by rw'; carries code
    int h = v;
    float rw = softplus(rot_scale[h]) * SCL;
    int code = (chain_id[token] << 16) | (seq_id[token] & 0xFFFF);
    g_QA[(size_t)((b*HH + h)*SS) + sl] =
        make_float4(o0*rw, o1*rw, o2*rw, __int_as_float(code));
  } else if (v < 32) {          // K rot, unscaled; carries masked code
    int h = v - 16;
    int code = (chain_id[token] << 16) | (seq_id[token] & 0xFFFF);
    int mc = (amask[token] != 0) ? code : -1;
    g_KA[(size_t)((b*HH + h)*SS) + sl] =
        make_float4(o0, o1, o2, __int_as_float(mc));
  } else if (v < 48) {          // V
    int h = v - 32;
    g_KV[(size_t)((b*HH + h)*SS) + sl] = make_float4(o0, o1, o2, 0.f);
  } else if (v < 64) {          // Q dist: +trans, scaled by dw'
    int h = v - 48;
    float dw = softplus(dist_scale[h]) * SCL;
    g_QB[(size_t)((b*HH + h)*SS) + sl] =
        make_float4((o0 + trans[token*3+0])*dw,
                    (o1 + trans[token*3+1])*dw,
                    (o2 + trans[token*3+2])*dw, 0.f);
  } else {                      // K dist: +trans, scaled by dw'
    int h = v - 64;
    float dw = softplus(dist_scale[h]) * SCL;
    g_KB[(size_t)((b*HH + h)*SS) + sl] =
        make_float4((o0 + trans[token*3+0])*dw,
                    (o1 + trans[token*3+1])*dw,
                    (o2 + trans[token*3+2])*dw, 0.f);
  }
}

// ---------------------------------------------------------------------------
// k2a: attention partials. block = (b, h, 64-q tile, k-half). 128 threads.
// K half-tile (512 k) staged once in smem, reused by 4 warps x 4 q-chunks.
// ---------------------------------------------------------------------------
__global__ __launch_bounds__(128) void k2a_attn(void)
{
  __shared__ float4 sKA[512];
  __shared__ float4 sKB[512];
  __shared__ float4 sKV[512];

  const float INVLN2 = 1.4426950408889634f;
  const int bid = blockIdx.x;
  const int kh  = bid & 1;                  // k half
  const int qt  = (bid >> 1) & 15;          // 16 tiles of 64 q rows
  const int h   = (bid >> 5) & 15;
  const int b   = bid >> 9;
  const int lane = threadIdx.x & 31;
  const int w    = threadIdx.x >> 5;        // 0..3

  const size_t base = (size_t)(b*HH + h)*SS;
  const float4* KA = g_KA + base + kh*512;
  const float4* KB = g_KB + base + kh*512;
  const float4* KV = g_KV + base + kh*512;
  const float4* QA = g_QA + base;
  const float4* QB = g_QB + base;
  float4* PART = (kh == 0 ? g_part0 : g_part1);

  #pragma unroll
  for (int i = 0; i < 4; i++) {
    int j = threadIdx.x + i*128;
    sKA[j] = KA[j];
    sKB[j] = KB[j];
    sKV[j] = KV[j];
  }
  __syncthreads();

  const int qwarp = qt*64 + w*16;
  #pragma unroll 1
  for (int chunk = 0; chunk < 4; chunk++) {
    const int q0 = qwarp + chunk*4;
    float qr0[4], qr1[4], qr2[4], qd0[4], qd1[4], qd2[4];
    int qcode[4], qch[4];
    #pragma unroll
    for (int r = 0; r < 4; r++) {
      float4 a  = QA[q0 + r];
      float4 dq = QB[q0 + r];
      qr0[r] = a.x;  qr1[r] = a.y;  qr2[r] = a.z;
      qcode[r] = __float_as_int(a.w);
      qch[r]   = qcode[r] >> 16;
      qd0[r] = dq.x; qd1[r] = dq.y; qd2[r] = dq.z;
    }
    float l[4], a0[4], a1[4], a2[4];
    #pragma unroll
    for (int r = 0; r < 4; r++) { l[r]=0.f; a0[r]=0.f; a1[r]=0.f; a2[r]=0.f; }

    #pragma unroll 4
    for (int ki = 0; ki < 16; ki++) {
      const int kk = ki*32 + lane;
      float4 ka = sKA[kk];
      float4 kb = sKB[kk];
      float4 kv = sKV[kk];
      int kcode  = __float_as_int(ka.w);
      int kchain = kcode >> 16;
      #pragma unroll
      for (int r = 0; r < 4; r++) {
        float rt  = qr0[r]*ka.x + qr1[r]*ka.y + qr2[r]*ka.z;
        float ddx = qd0[r]-kb.x, ddy = qd1[r]-kb.y, ddz = qd2[r]-kb.z;
        float d2  = ddx*ddx + ddy*ddy + ddz*ddz;
        float bias = (kcode == qcode[r]) ? INVLN2
                   : (kchain == qch[r] ? 0.0f : -1e30f);
        float sc = rt - fast_sqrt(d2) + bias;
        float p = fast_ex2(sc);
        l[r]  += p;
        a0[r] += p*kv.x; a1[r] += p*kv.y; a2[r] += p*kv.z;
      }
    }
    #pragma unroll
    for (int r = 0; r < 4; r++) {
      float L  = warp_sum(l[r]);
      float A0 = warp_sum(a0[r]);
      float A1 = warp_sum(a1[r]);
      float A2 = warp_sum(a2[r]);
      if (lane == r)
        PART[base + q0 + r] = make_float4(L, A0, A1, A2);
    }
  }
}

// ---------------------------------------------------------------------------
// k2b: merge k-halves, normalize, rotate back, mask, write g_att.
// one thread per (b,h,q).
// ---------------------------------------------------------------------------
__global__ __launch_bounds__(256) void k2b_reduce(
    const float* __restrict__ rot, const int* __restrict__ amask)
{
  int i = blockIdx.x*256 + threadIdx.x;      // BB*HH*SS
  int q = i & (SS-1);
  int h = (i >> 10) & (HH-1);
  int b = i >> 14;

  float4 p0 = g_part0[i];
  float4 p1 = g_part1[i];
  float inv = 1.f / (p0.x + p1.x);
  float o0 = (p0.y + p1.y) * inv;
  float o1 = (p0.z + p1.z) * inv;
  float o2 = (p0.w + p1.w) * inv;

  int row = b*SS + q;
  const float* R = rot + (size_t)row*9;
  float u0 = R[0]*o0 + R[3]*o1 + R[6]*o2;
  float u1 = R[1]*o0 + R[4]*o1 + R[7]*o2;
  float u2 = R[2]*o0 + R[5]*o1 + R[8]*o2;
  float mk = (amask[row] != 0) ? 1.f : 0.f;
  float* op = g_att + (size_t)row*48 + h*3;
  op[0] = u0*mk; op[1] = u1*mk; op[2] = u2*mk;
}

// ---------------------------------------------------------------------------
// k3: out[b,s,c] = sum_d att[b,s,d] * w_out[c,d]
// ---------------------------------------------------------------------------
__global__ __launch_bounds__(256) void k3_out(
    const float* __restrict__ w_out, float* __restrict__ out)
{
  __shared__ float w_s[48*64];    // [d][c]
  __shared__ float a_s[48*128];   // [d][r]
  const int tid = threadIdx.x;
  const int ct = blockIdx.x & 15, st = blockIdx.x >> 4;
  const int cb = ct*64, sb = st*128;

  for (int idx = tid; idx < 64*48; idx += 256) {
    int c = idx/48, d = idx - c*48;
    w_s[d*64 + c] = w_out[(size_t)(cb + c)*48 + d];
  }
  for (int idx = tid; idx < 128*48; idx += 256) {
    int r = idx/48, d = idx - r*48;
    a_s[d*128 + r] = g_att[(size_t)(sb + r)*48 + d];
  }
  __syncthreads();

  const int tx = tid & 15, ty = tid >> 4;
  float acc[8][4];
  #pragma unroll
  for (int i = 0; i < 8; i++)
    #pragma unroll
    for (int j = 0; j < 4; j++) acc[i][j] = 0.f;

  #pragma unroll 4
  for (int d = 0; d < 48; d++) {
    float4 wv = *(const float4*)&w_s[d*64 + tx*4];
    float4 aA = *(const float4*)&a_s[d*128 + ty*8];
    float4 aB = *(const float4*)&a_s[d*128 + ty*8 + 4];
    float av[8] = {aA.x, aA.y, aA.z, aA.w, aB.x, aB.y, aB.z, aB.w};
    #pragma unroll
    for (int i = 0; i < 8; i++) {
      acc[i][0] += av[i]*wv.x;
      acc[i][1] += av[i]*wv.y;
      acc[i][2] += av[i]*wv.z;
      acc[i][3] += av[i]*wv.w;
    }
  }
  #pragma unroll
  for (int i = 0; i < 8; i++) {
    float4 res = make_float4(acc[i][0], acc[i][1], acc[i][2], acc[i][3]);
    *(float4*)&out[(size_t)(sb + ty*8 + i)*1024 + cb + tx*4] = res;
  }
}

// ---------------------------------------------------------------------------
extern "C" void kernel_launch(void* const* d_in, const int* in_sizes, int n_in,
                              void* d_out, int out_size)
{
  const float* s          = (const float*)d_in[0];
  const float* rot        = (const float*)d_in[1];
  const float* trans      = (const float*)d_in[2];
  const float* ln_w       = (const float*)d_in[3];
  const float* w_proj     = (const float*)d_in[4];
  const float* w_out      = (const float*)d_in[5];
  const float* dist_scale = (const float*)d_in[6];
  const float* rot_scale  = (const float*)d_in[7];
  const int* am           = (const int*)d_in[8];
  const int* seq_id       = (const int*)d_in[9];
  const int* chain_id     = (const int*)d_in[10];
  float* out = (float*)d_out;

  k1a_stats  <<<256, 256>>>(s);
  k1b_gemm   <<<dim3(4,32), 256>>>(s, ln_w, w_proj);
  k1c_scatter<<<640, 256>>>(rot, trans, dist_scale, rot_scale, am, seq_id, chain_id);
  k2a_attn   <<<1024, 128>>>();
  k2b_reduce <<<128, 256>>>(rot, am);
  k3_out     <<<256, 256>>>(w_out, out);
}

// round 11
// speedup vs baseline: 1.7815x; 1.0589x over previous
#include <cuda_runtime.h>
#include <cstdint>

#define BB 2
#define SS 1024
#define CC 1024
#define HH 16

// scratch (device globals: no allocation allowed)
__device__ float g_mu[BB*SS];
__device__ float g_rs[BB*SS];
__device__ float g_wph[240*CC];             // w_proj tf32 hi
__device__ float g_wpl[240*CC];             // w_proj tf32 lo
__device__ float g_p[BB*SS*240];            // projection result [token][240]
// SoA float4 streams, indexed [(b*HH+h)*SS + k]
__device__ float4 g_QA[BB*HH*SS];           // {qr0*rw, qr1*rw, qr2*rw, code}
__device__ float4 g_QB[BB*HH*SS];           // {qd0*dw, qd1*dw, qd2*dw, 0}
__device__ float4 g_KA[BB*HH*SS];           // {kr0, kr1, kr2, codeMasked}
__device__ float4 g_KB[BB*HH*SS];           // {kd0*dw, kd1*dw, kd2*dw, 0}
__device__ float4 g_KV[BB*HH*SS];           // {v0, v1, v2, 0}
__device__ float4 g_part0[BB*HH*SS];        // k-half 0 partials {l, a0, a1, a2}
__device__ float4 g_part1[BB*HH*SS];        // k-half 1 partials

__device__ __forceinline__ float warp_sum(float v){
  #pragma unroll
  for (int o = 16; o > 0; o >>= 1) v += __shfl_xor_sync(0xffffffffu, v, o);
  return v;
}
__device__ __forceinline__ float fast_sqrt(float x){
  float r; asm("sqrt.approx.f32 %0, %1;" : "=f"(r) : "f"(x)); return r;
}
__device__ __forceinline__ float fast_ex2(float x){
  float r; asm("ex2.approx.f32 %0, %1;" : "=f"(r) : "f"(x)); return r;
}
__device__ __forceinline__ float softplus(float x){
  return x > 20.f ? x : log1pf(__expf(x));
}
__device__ __forceinline__ float tf32_rna(float x){
  uint32_t u; asm("cvt.rna.tf32.f32 %0, %1;" : "=r"(u) : "f"(x));
  return __uint_as_float(u);
}
__device__ __forceinline__ void mma_tf32(
    float& c0, float& c1, float& c2, float& c3,
    uint32_t a0, uint32_t a1, uint32_t a2, uint32_t a3,
    uint32_t b0, uint32_t b1)
{
  asm volatile("mma.sync.aligned.m16n8k8.row.col.f32.tf32.tf32.f32 "
      "{%0,%1,%2,%3}, {%4,%5,%6,%7}, {%8,%9}, {%0,%1,%2,%3};"
      : "+f"(c0), "+f"(c1), "+f"(c2), "+f"(c3)
      : "r"(a0), "r"(a1), "r"(a2), "r"(a3), "r"(b0), "r"(b1));
}

// ---------------------------------------------------------------------------
// k0: split w_proj into tf32 hi/lo (one float4 per thread).
// ---------------------------------------------------------------------------
__global__ __launch_bounds__(256) void k0_wsplit(const float* __restrict__ w)
{
  int i = (blockIdx.x*256 + threadIdx.x) * 4;   // 240*1024 / 4 = 61440 threads
  float4 x = *(const float4*)(w + i);
  float4 h, l;
  h.x = tf32_rna(x.x); l.x = tf32_rna(x.x - h.x);
  h.y = tf32_rna(x.y); l.y = tf32_rna(x.y - h.y);
  h.z = tf32_rna(x.z); l.z = tf32_rna(x.z - h.z);
  h.w = tf32_rna(x.w); l.w = tf32_rna(x.w - h.w);
  *(float4*)(g_wph + i) = h;
  *(float4*)(g_wpl + i) = l;
}

// ---------------------------------------------------------------------------
// k1a: per-row layernorm stats. one warp per row.
// ---------------------------------------------------------------------------
__global__ __launch_bounds__(256) void k1a_stats(const float* __restrict__ s)
{
  const int lane = threadIdx.x & 31;
  const int row  = blockIdx.x*8 + (threadIdx.x >> 5);
  const float* sr = s + (size_t)row * CC;
  float sum = 0.f, sq = 0.f;
  #pragma unroll
  for (int i = 0; i < 8; i++) {
    float4 v = *(const float4*)(sr + i*128 + lane*4);
    sum += v.x + v.y + v.z + v.w;
    sq  += v.x*v.x + v.y*v.y + v.z*v.z + v.w*v.w;
  }
  sum = warp_sum(sum); sq = warp_sum(sq);
  if (lane == 0) {
    float mean = sum * (1.f/CC);
    float var  = sq * (1.f/CC) - mean*mean;
    g_mu[row] = mean;
    g_rs[row] = rsqrtf(var + 1e-5f);
  }
}

// ---------------------------------------------------------------------------
// k1b: 3xTF32 mma GEMM. p[r][d] = sum_c ns[r][c]*W[d][c].
// BM=64, BN=64 (240 padded to 256), BK=32. 8 warps; warp = m16 x n32.
// ---------------------------------------------------------------------------
#define KST 36
__global__ __launch_bounds__(256) void k1b_gemm(
    const float* __restrict__ s, const float* __restrict__ ln_w)
{
  __shared__ __align__(16) float Ah[64*KST];
  __shared__ __align__(16) float Al[64*KST];
  __shared__ __align__(16) float Bh[64*KST];
  __shared__ __align__(16) float Bl[64*KST];
  __shared__ float mu_s[64], rs_s[64];

  const int t   = threadIdx.x;
  const int bx  = blockIdx.x;          // n-tile 0..3
  const int by  = blockIdx.y;          // m-tile 0..31
  const int wrp = t >> 5;
  const int lane= t & 31;
  const int mw  = wrp & 3;             // m16 index
  const int nh  = wrp >> 2;            // n32 half
  const int g   = lane >> 2;           // group id
  const int tig = lane & 3;            // thread in group

  const int frow = t >> 2;             // staging row 0..63
  const int fcol = (t & 3) * 8;        // staging col group

  if (t < 64) { mu_s[t] = g_mu[by*64 + t]; rs_s[t] = g_rs[by*64 + t]; }

  float acc[4][4];
  #pragma unroll
  for (int j = 0; j < 4; j++)
    #pragma unroll
    for (int i = 0; i < 4; i++) acc[j][i] = 0.f;

  for (int kc = 0; kc < 32; kc++) {
    __syncthreads();
    // ---- stage A (normalized s) hi/lo ----
    {
      const int cg = kc*32 + fcol;
      float4 sv0 = *(const float4*)(s + (size_t)(by*64 + frow)*CC + cg);
      float4 sv1 = *(const float4*)(s + (size_t)(by*64 + frow)*CC + cg + 4);
      float4 lw0 = *(const float4*)(ln_w + cg);
      float4 lw1 = *(const float4*)(ln_w + cg + 4);
      float m_ = mu_s[frow], rr = rs_s[frow];
      float v[8] = {(sv0.x-m_)*rr*lw0.x, (sv0.y-m_)*rr*lw0.y,
                    (sv0.z-m_)*rr*lw0.z, (sv0.w-m_)*rr*lw0.w,
                    (sv1.x-m_)*rr*lw1.x, (sv1.y-m_)*rr*lw1.y,
                    (sv1.z-m_)*rr*lw1.z, (sv1.w-m_)*rr*lw1.w};
      float hv[8], lv[8];
      #pragma unroll
      for (int i = 0; i < 8; i++) {
        hv[i] = tf32_rna(v[i]);
        lv[i] = tf32_rna(v[i] - hv[i]);
      }
      *(float4*)&Ah[frow*KST + fcol]     = make_float4(hv[0],hv[1],hv[2],hv[3]);
      *(float4*)&Ah[frow*KST + fcol + 4] = make_float4(hv[4],hv[5],hv[6],hv[7]);
      *(float4*)&Al[frow*KST + fcol]     = make_float4(lv[0],lv[1],lv[2],lv[3]);
      *(float4*)&Al[frow*KST + fcol + 4] = make_float4(lv[4],lv[5],lv[6],lv[7]);
      // ---- stage B (w_proj hi/lo, pre-split) ----
      int dg = bx*64 + frow;
      float4 bh0 = make_float4(0,0,0,0), bh1 = bh0, bl0 = bh0, bl1 = bh0;
      if (dg < 240) {
        bh0 = *(const float4*)(g_wph + (size_t)dg*CC + cg);
        bh1 = *(const float4*)(g_wph + (size_t)dg*CC + cg + 4);
        bl0 = *(const float4*)(g_wpl + (size_t)dg*CC + cg);
        bl1 = *(const float4*)(g_wpl + (size_t)dg*CC + cg + 4);
      }
      *(float4*)&Bh[frow*KST + fcol]     = bh0;
      *(float4*)&Bh[frow*KST + fcol + 4] = bh1;
      *(float4*)&Bl[frow*KST + fcol]     = bl0;
      *(float4*)&Bl[frow*KST + fcol + 4] = bl1;
    }
    __syncthreads();

    // ---- mma over 4 k8 steps ----
    #pragma unroll
    for (int st = 0; st < 4; st++) {
      const int k0 = st*8;
      const int ar0 = (mw*16 + g)*KST + k0 + tig;
      const int ar1 = ar0 + 8*KST;
      uint32_t ah0 = __float_as_uint(Ah[ar0]);
      uint32_t ah1 = __float_as_uint(Ah[ar1]);
      uint32_t ah2 = __float_as_uint(Ah[ar0 + 4]);
      uint32_t ah3 = __float_as_uint(Ah[ar1 + 4]);
      uint32_t al0 = __float_as_uint(Al[ar0]);
      uint32_t al1 = __float_as_uint(Al[ar1]);
      uint32_t al2 = __float_as_uint(Al[ar0 + 4]);
      uint32_t al3 = __float_as_uint(Al[ar1 + 4]);
      #pragma unroll
      for (int j = 0; j < 4; j++) {
        const int br = (nh*32 + j*8 + g)*KST + k0 + tig;
        uint32_t bh0 = __float_as_uint(Bh[br]);
        uint32_t bh1 = __float_as_uint(Bh[br + 4]);
        uint32_t bl0 = __float_as_uint(Bl[br]);
        uint32_t bl1 = __float_as_uint(Bl[br + 4]);
        mma_tf32(acc[j][0], acc[j][1], acc[j][2], acc[j][3],
                 ah0, ah1, ah2, ah3, bh0, bh1);
        mma_tf32(acc[j][0], acc[j][1], acc[j][2], acc[j][3],
                 ah0, ah1, ah2, ah3, bl0, bl1);
        mma_tf32(acc[j][0], acc[j][1], acc[j][2], acc[j][3],
                 al0, al1, al2, al3, bh0, bh1);
      }
    }
  }

  // ---- epilogue: c0/c1 at (r0, c), c2/c3 at (r0+8, c) ----
  const int r0 = by*64 + mw*16 + g;
  #pragma unroll
  for (int j = 0; j < 4; j++) {
    int c = bx*64 + nh*32 + j*8 + 2*tig;
    if (c < 240) {
      *(float2*)&g_p[(size_t)r0*240 + c]       = make_float2(acc[j][0], acc[j][1]);
      *(float2*)&g_p[(size_t)(r0+8)*240 + c]   = make_float2(acc[j][2], acc[j][3]);
    }
  }
}

// ---------------------------------------------------------------------------
// k1c: rotate 3-vectors, fold all softmax scales, scatter to SoA Q/K layout.
// ---------------------------------------------------------------------------
__global__ __launch_bounds__(256) void k1c_scatter(
    const float* __restrict__ rot, const float* __restrict__ trans,
    const float* __restrict__ dist_scale, const float* __restrict__ rot_scale,
    const int* __restrict__ amask,
    const int* __restrict__ seq_id, const int* __restrict__ chain_id)
{
  const float SCL = 1.4426950408889634f / 1.7320508075688772f; // invln2/sqrt3
  int idx = blockIdx.x*256 + threadIdx.x;      // 2048*80 total
  int token = idx / 80;
  int v = idx - token*80;
  int b = token >> 10, sl = token & 1023;

  const float* P = g_p + (size_t)token*240 + v*3;
  float x = P[0], y = P[1], z = P[2];
  const float* R = rot + (size_t)token*9;
  float o0 = R[0]*x + R[1]*y + R[2]*z;
  float o1 = R[3]*x + R[4]*y + R[5]*z;
  float o2 = R[6]*x + R[7]*y + R[8]*z;

  if (v < 16) {                 // Q rot, scaled by rw'; carries code
    int h = v;
    float rw = softplus(rot_scale[h]) * SCL;
    int code = (chain_id[token] << 16) | (seq_id[token] & 0xFFFF);
    g_QA[(size_t)((b*HH + h)*SS) + sl] =
        make_float4(o0*rw, o1*rw, o2*rw, __int_as_float(code));
  } else if (v < 32) {          // K rot, unscaled; carries masked code
    int h = v - 16;
    int code = (chain_id[token] << 16) | (seq_id[token] & 0xFFFF);
    int mc = (amask[token] != 0) ? code : -1;
    g_KA[(size_t)((b*HH + h)*SS) + sl] =
        make_float4(o0, o1, o2, __int_as_float(mc));
  } else if (v < 48) {          // V
    int h = v - 32;
    g_KV[(size_t)((b*HH + h)*SS) + sl] = make_float4(o0, o1, o2, 0.f);
  } else if (v < 64) {          // Q dist: +trans, scaled by dw'
    int h = v - 48;
    float dw = softplus(dist_scale[h]) * SCL;
    g_QB[(size_t)((b*HH + h)*SS) + sl] =
        make_float4((o0 + trans[token*3+0])*dw,
                    (o1 + trans[token*3+1])*dw,
                    (o2 + trans[token*3+2])*dw, 0.f);
  } else {                      // K dist: +trans, scaled by dw'
    int h = v - 64;
    float dw = softplus(dist_scale[h]) * SCL;
    g_KB[(size_t)((b*HH + h)*SS) + sl] =
        make_float4((o0 + trans[token*3+0])*dw,
                    (o1 + trans[token*3+1])*dw,
                    (o2 + trans[token*3+2])*dw, 0.f);
  }
}

// ---------------------------------------------------------------------------
// k2a: attention partials. block = (b, h, 64-q tile, k-half). 128 threads.
// K half-tile (512 k) staged once in smem, reused by 4 warps x 4 q-chunks.
// ---------------------------------------------------------------------------
__global__ __launch_bounds__(128) void k2a_attn(void)
{
  __shared__ float4 sKA[512];
  __shared__ float4 sKB[512];
  __shared__ float4 sKV[512];

  const float INVLN2 = 1.4426950408889634f;
  const int bid = blockIdx.x;
  const int kh  = bid & 1;                  // k half
  const int qt  = (bid >> 1) & 15;          // 16 tiles of 64 q rows
  const int h   = (bid >> 5) & 15;
  const int b   = bid >> 9;
  const int lane = threadIdx.x & 31;
  const int w    = threadIdx.x >> 5;        // 0..3

  const size_t base = (size_t)(b*HH + h)*SS;
  const float4* KA = g_KA + base + kh*512;
  const float4* KB = g_KB + base + kh*512;
  const float4* KV = g_KV + base + kh*512;
  const float4* QA = g_QA + base;
  const float4* QB = g_QB + base;
  float4* PART = (kh == 0 ? g_part0 : g_part1);

  #pragma unroll
  for (int i = 0; i < 4; i++) {
    int j = threadIdx.x + i*128;
    sKA[j] = KA[j];
    sKB[j] = KB[j];
    sKV[j] = KV[j];
  }
  __syncthreads();

  const int qwarp = qt*64 + w*16;
  #pragma unroll 1
  for (int chunk = 0; chunk < 4; chunk++) {
    const int q0 = qwarp + chunk*4;
    float qr0[4], qr1[4], qr2[4], qd0[4], qd1[4], qd2[4];
    int qcode[4], qch[4];
    #pragma unroll
    for (int r = 0; r < 4; r++) {
      float4 a  = QA[q0 + r];
      float4 dq = QB[q0 + r];
      qr0[r] = a.x;  qr1[r] = a.y;  qr2[r] = a.z;
      qcode[r] = __float_as_int(a.w);
      qch[r]   = qcode[r] >> 16;
      qd0[r] = dq.x; qd1[r] = dq.y; qd2[r] = dq.z;
    }
    float l[4], a0[4], a1[4], a2[4];
    #pragma unroll
    for (int r = 0; r < 4; r++) { l[r]=0.f; a0[r]=0.f; a1[r]=0.f; a2[r]=0.f; }

    #pragma unroll 4
    for (int ki = 0; ki < 16; ki++) {
      const int kk = ki*32 + lane;
      float4 ka = sKA[kk];
      float4 kb = sKB[kk];
      float4 kv = sKV[kk];
      int kcode  = __float_as_int(ka.w);
      int kchain = kcode >> 16;
      #pragma unroll
      for (int r = 0; r < 4; r++) {
        float rt  = qr0[r]*ka.x + qr1[r]*ka.y + qr2[r]*ka.z;
        float ddx = qd0[r]-kb.x, ddy = qd1[r]-kb.y, ddz = qd2[r]-kb.z;
        float d2  = ddx*ddx + ddy*ddy + ddz*ddz;
        float bias = (kcode == qcode[r]) ? INVLN2
                   : (kchain == qch[r] ? 0.0f : -1e30f);
        float sc = rt - fast_sqrt(d2) + bias;
        float p = fast_ex2(sc);
        l[r]  += p;
        a0[r] += p*kv.x; a1[r] += p*kv.y; a2[r] += p*kv.z;
      }
    }
    #pragma unroll
    for (int r = 0; r < 4; r++) {
      float L  = warp_sum(l[r]);
      float A0 = warp_sum(a0[r]);
      float A1 = warp_sum(a1[r]);
      float A2 = warp_sum(a2[r]);
      if (lane == r)
        PART[base + q0 + r] = make_float4(L, A0, A1, A2);
    }
  }
}

// ---------------------------------------------------------------------------
// k3: fused partial-merge + back-rotation + mask + output GEMM.
// out[b,s,c] = sum_d att[b,s,d] * w_out[c,d]
// ---------------------------------------------------------------------------
__global__ __launch_bounds__(256) void k3_out(
    const float* __restrict__ rot, const int* __restrict__ amask,
    const float* __restrict__ w_out, float* __restrict__ out)
{
  __shared__ float w_s[48*64];    // [d][c]
  __shared__ float a_s[48*128];   // [d][r]
  __shared__ float rot_s[128*9];
  const int tid = threadIdx.x;
  const int ct = blockIdx.x & 15, st = blockIdx.x >> 4;
  const int cb = ct*64, sb = st*128;

  for (int idx = tid; idx < 64*48; idx += 256) {
    int c = idx/48, d = idx - c*48;
    w_s[d*64 + c] = w_out[(size_t)(cb + c)*48 + d];
  }
  for (int idx = tid; idx < 128*9; idx += 256)
    rot_s[idx] = rot[(size_t)sb*9 + idx];
  __syncthreads();

  // merge k-half partials -> normalize -> back-rotate -> mask -> a_s
  for (int i = tid; i < 128*16; i += 256) {
    int r = i & 127, h = i >> 7;
    int row = sb + r;
    int b = row >> 10, q = row & 1023;
    int idx = ((b*HH + h) << 10) + q;
    float4 p0 = g_part0[idx];
    float4 p1 = g_part1[idx];
    float inv = 1.f / (p0.x + p1.x);
    float o0 = (p0.y + p1.y) * inv;
    float o1 = (p0.z + p1.z) * inv;
    float o2 = (p0.w + p1.w) * inv;
    const float* R = &rot_s[r*9];
    float mk = (amask[row] != 0) ? 1.f : 0.f;
    a_s[(h*3+0)*128 + r] = (R[0]*o0 + R[3]*o1 + R[6]*o2) * mk;
    a_s[(h*3+1)*128 + r] = (R[1]*o0 + R[4]*o1 + R[7]*o2) * mk;
    a_s[(h*3+2)*128 + r] = (R[2]*o0 + R[5]*o1 + R[8]*o2) * mk;
  }
  __syncthreads();

  const int tx = tid & 15, ty = tid >> 4;
  float acc[8][4];
  #pragma unroll
  for (int i = 0; i < 8; i++)
    #pragma unroll
    for (int j = 0; j < 4; j++) acc[i][j] = 0.f;

  #pragma unroll 4
  for (int d = 0; d < 48; d++) {
    float4 wv = *(const float4*)&w_s[d*64 + tx*4];
    float4 aA = *(const float4*)&a_s[d*128 + ty*8];
    float4 aB = *(const float4*)&a_s[d*128 + ty*8 + 4];
    float av[8] = {aA.x, aA.y, aA.z, aA.w, aB.x, aB.y, aB.z, aB.w};
    #pragma unroll
    for (int i = 0; i < 8; i++) {
      acc[i][0] += av[i]*wv.x;
      acc[i][1] += av[i]*wv.y;
      acc[i][2] += av[i]*wv.z;
      acc[i][3] += av[i]*wv.w;
    }
  }
  #pragma unroll
  for (int i = 0; i < 8; i++) {
    float4 res = make_float4(acc[i][0], acc[i][1], acc[i][2], acc[i][3]);
    *(float4*)&out[(size_t)(sb + ty*8 + i)*1024 + cb + tx*4] = res;
  }
}

// ---------------------------------------------------------------------------
extern "C" void kernel_launch(void* const* d_in, const int* in_sizes, int n_in,
                              void* d_out, int out_size)
{
  const float* s          = (const float*)d_in[0];
  const float* rot        = (const float*)d_in[1];
  const float* trans      = (const float*)d_in[2];
  const float* ln_w       = (const float*)d_in[3];
  const float* w_proj     = (const float*)d_in[4];
  const float* w_out      = (const float*)d_in[5];
  const float* dist_scale = (const float*)d_in[6];
  const float* rot_scale  = (const float*)d_in[7];
  const int* am           = (const int*)d_in[8];
  const int* seq_id       = (const int*)d_in[9];
  const int* chain_id     = (const int*)d_in[10];
  float* out = (float*)d_out;

  k0_wsplit  <<<240, 256>>>(w_proj);
  k1a_stats  <<<256, 256>>>(s);
  k1b_gemm   <<<dim3(4,32), 256>>>(s, ln_w);
  k1c_scatter<<<640, 256>>>(rot, trans, dist_scale, rot_scale, am, seq_id, chain_id);
  k2a_attn   <<<1024, 128>>>();
  k3_out     <<<256, 256>>>(rot, am, w_out, out);
}

// round 12
// speedup vs baseline: 1.8302x; 1.0273x over previous
#include <cuda_runtime.h>
#include <cstdint>

#define BB 2
#define SS 1024
#define CC 1024
#define HH 16

// scratch (device globals: no allocation allowed)
__device__ float g_mu[BB*SS];
__device__ float g_rs[BB*SS];
__device__ float g_wph[240*CC];             // w_proj tf32 hi
__device__ float g_wpl[240*CC];             // w_proj tf32 lo
__device__ float g_p[BB*SS*240];            // projection result [token][240]
// SoA float4 streams, indexed [(b*HH+h)*SS + k]
__device__ float4 g_QA[BB*HH*SS];           // {qr0*rw, qr1*rw, qr2*rw, code}
__device__ float4 g_QB[BB*HH*SS];           // {qd0*dw, qd1*dw, qd2*dw, qq}
__device__ float4 g_KA[BB*HH*SS];           // {kr0, kr1, kr2, codeMasked}
__device__ float4 g_KB[BB*HH*SS];           // {-2kd0*dw, -2kd1*dw, -2kd2*dw, kk}
__device__ float4 g_KV[BB*HH*SS];           // {v0, v1, v2, 0}
__device__ float4 g_part0[BB*HH*SS];        // k-half 0 partials {l, a0, a1, a2}
__device__ float4 g_part1[BB*HH*SS];        // k-half 1 partials

__device__ __forceinline__ float warp_sum(float v){
  #pragma unroll
  for (int o = 16; o > 0; o >>= 1) v += __shfl_xor_sync(0xffffffffu, v, o);
  return v;
}
__device__ __forceinline__ float fast_sqrt(float x){
  float r; asm("sqrt.approx.f32 %0, %1;" : "=f"(r) : "f"(x)); return r;
}
__device__ __forceinline__ float fast_ex2(float x){
  float r; asm("ex2.approx.f32 %0, %1;" : "=f"(r) : "f"(x)); return r;
}
__device__ __forceinline__ float softplus(float x){
  return x > 20.f ? x : log1pf(__expf(x));
}
__device__ __forceinline__ float tf32_rna(float x){
  uint32_t u; asm("cvt.rna.tf32.f32 %0, %1;" : "=r"(u) : "f"(x));
  return __uint_as_float(u);
}
__device__ __forceinline__ void mma_tf32(
    float& c0, float& c1, float& c2, float& c3,
    uint32_t a0, uint32_t a1, uint32_t a2, uint32_t a3,
    uint32_t b0, uint32_t b1)
{
  asm volatile("mma.sync.aligned.m16n8k8.row.col.f32.tf32.tf32.f32 "
      "{%0,%1,%2,%3}, {%4,%5,%6,%7}, {%8,%9}, {%0,%1,%2,%3};"
      : "+f"(c0), "+f"(c1), "+f"(c2), "+f"(c3)
      : "r"(a0), "r"(a1), "r"(a2), "r"(a3), "r"(b0), "r"(b1));
}

// ---------------------------------------------------------------------------
// k1a: per-row layernorm stats (one warp per row) + w_proj tf32 hi/lo split.
// ---------------------------------------------------------------------------
__global__ __launch_bounds__(256) void k1a_stats(
    const float* __restrict__ s, const float* __restrict__ w)
{
  const int lane = threadIdx.x & 31;
  const int row  = blockIdx.x*8 + (threadIdx.x >> 5);
  const float* sr = s + (size_t)row * CC;
  float sum = 0.f, sq = 0.f;
  #pragma unroll
  for (int i = 0; i < 8; i++) {
    float4 v = *(const float4*)(sr + i*128 + lane*4);
    sum += v.x + v.y + v.z + v.w;
    sq  += v.x*v.x + v.y*v.y + v.z*v.z + v.w*v.w;
  }
  sum = warp_sum(sum); sq = warp_sum(sq);
  if (lane == 0) {
    float mean = sum * (1.f/CC);
    float var  = sq * (1.f/CC) - mean*mean;
    g_mu[row] = mean;
    g_rs[row] = rsqrtf(var + 1e-5f);
  }

  // appended: split w_proj into tf32 hi/lo (61440 float4 groups < 65536 thr)
  int i = blockIdx.x*256 + threadIdx.x;
  if (i < 61440) {
    int e = i*4;
    float4 x = *(const float4*)(w + e);
    float4 h, l;
    h.x = tf32_rna(x.x); l.x = tf32_rna(x.x - h.x);
    h.y = tf32_rna(x.y); l.y = tf32_rna(x.y - h.y);
    h.z = tf32_rna(x.z); l.z = tf32_rna(x.z - h.z);
    h.w = tf32_rna(x.w); l.w = tf32_rna(x.w - h.w);
    *(float4*)(g_wph + e) = h;
    *(float4*)(g_wpl + e) = l;
  }
}

// ---------------------------------------------------------------------------
// k1b: 3xTF32 mma GEMM. p[r][d] = sum_c ns[r][c]*W[d][c].
// BM=64, BN=64 (240 padded to 256), BK=32. 8 warps; warp = m16 x n32.
// ---------------------------------------------------------------------------
#define KST 36
__global__ __launch_bounds__(256) void k1b_gemm(
    const float* __restrict__ s, const float* __restrict__ ln_w)
{
  __shared__ __align__(16) float Ah[64*KST];
  __shared__ __align__(16) float Al[64*KST];
  __shared__ __align__(16) float Bh[64*KST];
  __shared__ __align__(16) float Bl[64*KST];
  __shared__ float mu_s[64], rs_s[64];

  const int t   = threadIdx.x;
  const int bx  = blockIdx.x;          // n-tile 0..3
  const int by  = blockIdx.y;          // m-tile 0..31
  const int wrp = t >> 5;
  const int lane= t & 31;
  const int mw  = wrp & 3;             // m16 index
  const int nh  = wrp >> 2;            // n32 half
  const int g   = lane >> 2;           // group id
  const int tig = lane & 3;            // thread in group

  const int frow = t >> 2;             // staging row 0..63
  const int fcol = (t & 3) * 8;        // staging col group

  if (t < 64) { mu_s[t] = g_mu[by*64 + t]; rs_s[t] = g_rs[by*64 + t]; }

  float acc[4][4];
  #pragma unroll
  for (int j = 0; j < 4; j++)
    #pragma unroll
    for (int i = 0; i < 4; i++) acc[j][i] = 0.f;

  for (int kc = 0; kc < 32; kc++) {
    __syncthreads();
    // ---- stage A (normalized s) hi/lo ----
    {
      const int cg = kc*32 + fcol;
      float4 sv0 = *(const float4*)(s + (size_t)(by*64 + frow)*CC + cg);
      float4 sv1 = *(const float4*)(s + (size_t)(by*64 + frow)*CC + cg + 4);
      float4 lw0 = *(const float4*)(ln_w + cg);
      float4 lw1 = *(const float4*)(ln_w + cg + 4);
      float m_ = mu_s[frow], rr = rs_s[frow];
      float v[8] = {(sv0.x-m_)*rr*lw0.x, (sv0.y-m_)*rr*lw0.y,
                    (sv0.z-m_)*rr*lw0.z, (sv0.w-m_)*rr*lw0.w,
                    (sv1.x-m_)*rr*lw1.x, (sv1.y-m_)*rr*lw1.y,
                    (sv1.z-m_)*rr*lw1.z, (sv1.w-m_)*rr*lw1.w};
      float hv[8], lv[8];
      #pragma unroll
      for (int i = 0; i < 8; i++) {
        hv[i] = tf32_rna(v[i]);
        lv[i] = tf32_rna(v[i] - hv[i]);
      }
      *(float4*)&Ah[frow*KST + fcol]     = make_float4(hv[0],hv[1],hv[2],hv[3]);
      *(float4*)&Ah[frow*KST + fcol + 4] = make_float4(hv[4],hv[5],hv[6],hv[7]);
      *(float4*)&Al[frow*KST + fcol]     = make_float4(lv[0],lv[1],lv[2],lv[3]);
      *(float4*)&Al[frow*KST + fcol + 4] = make_float4(lv[4],lv[5],lv[6],lv[7]);
      // ---- stage B (w_proj hi/lo, pre-split) ----
      int dg = bx*64 + frow;
      float4 bh0 = make_float4(0,0,0,0), bh1 = bh0, bl0 = bh0, bl1 = bh0;
      if (dg < 240) {
        bh0 = *(const float4*)(g_wph + (size_t)dg*CC + cg);
        bh1 = *(const float4*)(g_wph + (size_t)dg*CC + cg + 4);
        bl0 = *(const float4*)(g_wpl + (size_t)dg*CC + cg);
        bl1 = *(const float4*)(g_wpl + (size_t)dg*CC + cg + 4);
      }
      *(float4*)&Bh[frow*KST + fcol]     = bh0;
      *(float4*)&Bh[frow*KST + fcol + 4] = bh1;
      *(float4*)&Bl[frow*KST + fcol]     = bl0;
      *(float4*)&Bl[frow*KST + fcol + 4] = bl1;
    }
    __syncthreads();

    // ---- mma over 4 k8 steps ----
    #pragma unroll
    for (int st = 0; st < 4; st++) {
      const int k0 = st*8;
      const int ar0 = (mw*16 + g)*KST + k0 + tig;
      const int ar1 = ar0 + 8*KST;
      uint32_t ah0 = __float_as_uint(Ah[ar0]);
      uint32_t ah1 = __float_as_uint(Ah[ar1]);
      uint32_t ah2 = __float_as_uint(Ah[ar0 + 4]);
      uint32_t ah3 = __float_as_uint(Ah[ar1 + 4]);
      uint32_t al0 = __float_as_uint(Al[ar0]);
      uint32_t al1 = __float_as_uint(Al[ar1]);
      uint32_t al2 = __float_as_uint(Al[ar0 + 4]);
      uint32_t al3 = __float_as_uint(Al[ar1 + 4]);
      #pragma unroll
      for (int j = 0; j < 4; j++) {
        const int br = (nh*32 + j*8 + g)*KST + k0 + tig;
        uint32_t bh0 = __float_as_uint(Bh[br]);
        uint32_t bh1 = __float_as_uint(Bh[br + 4]);
        uint32_t bl0 = __float_as_uint(Bl[br]);
        uint32_t bl1 = __float_as_uint(Bl[br + 4]);
        mma_tf32(acc[j][0], acc[j][1], acc[j][2], acc[j][3],
                 ah0, ah1, ah2, ah3, bh0, bh1);
        mma_tf32(acc[j][0], acc[j][1], acc[j][2], acc[j][3],
                 ah0, ah1, ah2, ah3, bl0, bl1);
        mma_tf32(acc[j][0], acc[j][1], acc[j][2], acc[j][3],
                 al0, al1, al2, al3, bh0, bh1);
      }
    }
  }

  // ---- epilogue: c0/c1 at (r0, c), c2/c3 at (r0+8, c) ----
  const int r0 = by*64 + mw*16 + g;
  #pragma unroll
  for (int j = 0; j < 4; j++) {
    int c = bx*64 + nh*32 + j*8 + 2*tig;
    if (c < 240) {
      *(float2*)&g_p[(size_t)r0*240 + c]       = make_float2(acc[j][0], acc[j][1]);
      *(float2*)&g_p[(size_t)(r0+8)*240 + c]   = make_float2(acc[j][2], acc[j][3]);
    }
  }
}

// ---------------------------------------------------------------------------
// k1c: rotate 3-vectors, fold scales, scatter to SoA Q/K layout.
// block = 16 tokens; all operands staged in smem; warp-coalesced stores.
// ---------------------------------------------------------------------------
__global__ __launch_bounds__(256) void k1c_scatter(
    const float* __restrict__ rot, const float* __restrict__ trans,
    const float* __restrict__ dist_scale, const float* __restrict__ rot_scale,
    const int* __restrict__ amask,
    const int* __restrict__ seq_id, const int* __restrict__ chain_id)
{
  __shared__ float p_s[16*240];
  __shared__ float rot_s[16*9];
  __shared__ float trans_s[16*3];
  __shared__ int   code_s[16];
  __shared__ int   mask_s[16];
  __shared__ float rw_s[16], dw_s[16];

  const float SCL = 1.4426950408889634f / 1.7320508075688772f; // invln2/sqrt3
  const int tid = threadIdx.x;
  const int tb  = blockIdx.x * 16;     // 128 blocks

  for (int i = tid; i < 960; i += 256)
    *(float4*)&p_s[i*4] = *(const float4*)&g_p[(size_t)tb*240 + i*4];
  for (int i = tid; i < 144; i += 256)
    rot_s[i] = rot[(size_t)tb*9 + i];
  if (tid < 48) trans_s[tid] = trans[tb*3 + tid];
  if (tid < 16) {
    code_s[tid] = (chain_id[tb+tid] << 16) | (seq_id[tb+tid] & 0xFFFF);
    mask_s[tid] = amask[tb+tid];
    rw_s[tid] = softplus(rot_scale[tid]) * SCL;
    dw_s[tid] = softplus(dist_scale[tid]) * SCL;
  }
  __syncthreads();

  const int b  = tb >> 10;
  const int s0 = tb & 1023;
  #pragma unroll
  for (int it = 0; it < 5; it++) {
    int item = it*256 + tid;           // 1280 = 80 vecs x 16 tokens
    int v = item >> 4, t = item & 15;
    int sl = s0 + t;
    const float* P = &p_s[t*240 + v*3];
    float x = P[0], y = P[1], z = P[2];
    const float* R = &rot_s[t*9];
    float o0 = R[0]*x + R[1]*y + R[2]*z;
    float o1 = R[3]*x + R[4]*y + R[5]*z;
    float o2 = R[6]*x + R[7]*y + R[8]*z;

    if (v < 16) {                 // Q rot, scaled by rw'; carries code
      int h = v;
      float rw = rw_s[h];
      g_QA[(size_t)((b*HH + h)*SS) + sl] =
          make_float4(o0*rw, o1*rw, o2*rw, __int_as_float(code_s[t]));
    } else if (v < 32) {          // K rot, unscaled; carries masked code
      int h = v - 16;
      int mc = mask_s[t] ? code_s[t] : -1;
      g_KA[(size_t)((b*HH + h)*SS) + sl] =
          make_float4(o0, o1, o2, __int_as_float(mc));
    } else if (v < 48) {          // V
      int h = v - 32;
      g_KV[(size_t)((b*HH + h)*SS) + sl] = make_float4(o0, o1, o2, 0.f);
    } else if (v < 64) {          // Q dist: +trans, scaled by dw'; qq in .w
      int h = v - 48;
      float dw = dw_s[h];
      float d0 = (o0 + trans_s[t*3+0])*dw;
      float d1 = (o1 + trans_s[t*3+1])*dw;
      float d2 = (o2 + trans_s[t*3+2])*dw;
      g_QB[(size_t)((b*HH + h)*SS) + sl] =
          make_float4(d0, d1, d2, d0*d0 + d1*d1 + d2*d2);
    } else {                      // K dist: store {-2kd', kk'}
      int h = v - 64;
      float dw = dw_s[h];
      float d0 = (o0 + trans_s[t*3+0])*dw;
      float d1 = (o1 + trans_s[t*3+1])*dw;
      float d2 = (o2 + trans_s[t*3+2])*dw;
      g_KB[(size_t)((b*HH + h)*SS) + sl] =
          make_float4(-2.f*d0, -2.f*d1, -2.f*d2, d0*d0 + d1*d1 + d2*d2);
    }
  }
}

// ---------------------------------------------------------------------------
// k2a: attention partials. block = (b, h, 64-q tile, k-half). 128 threads.
// K half-tile (512 k) staged once in smem, reused by 4 warps x 4 q-chunks.
// d2 via expanded form: d2 = qq + kk - 2 qd.kd  (clamped >= 0).
// ---------------------------------------------------------------------------
__global__ __launch_bounds__(128) void k2a_attn(void)
{
  __shared__ float4 sKA[512];
  __shared__ float4 sKB[512];
  __shared__ float4 sKV[512];

  const float INVLN2 = 1.4426950408889634f;
  const int bid = blockIdx.x;
  const int kh  = bid & 1;                  // k half
  const int qt  = (bid >> 1) & 15;          // 16 tiles of 64 q rows
  const int h   = (bid >> 5) & 15;
  const int b   = bid >> 9;
  const int lane = threadIdx.x & 31;
  const int w    = threadIdx.x >> 5;        // 0..3

  const size_t base = (size_t)(b*HH + h)*SS;
  const float4* KA = g_KA + base + kh*512;
  const float4* KB = g_KB + base + kh*512;
  const float4* KV = g_KV + base + kh*512;
  const float4* QA = g_QA + base;
  const float4* QB = g_QB + base;
  float4* PART = (kh == 0 ? g_part0 : g_part1);

  #pragma unroll
  for (int i = 0; i < 4; i++) {
    int j = threadIdx.x + i*128;
    sKA[j] = KA[j];
    sKB[j] = KB[j];
    sKV[j] = KV[j];
  }
  __syncthreads();

  const int qwarp = qt*64 + w*16;
  #pragma unroll 1
  for (int chunk = 0; chunk < 4; chunk++) {
    const int q0 = qwarp + chunk*4;
    float qr0[4], qr1[4], qr2[4], qd0[4], qd1[4], qd2[4], qq[4];
    int qcode[4], qch[4];
    #pragma unroll
    for (int r = 0; r < 4; r++) {
      float4 a  = QA[q0 + r];
      float4 dq = QB[q0 + r];
      qr0[r] = a.x;  qr1[r] = a.y;  qr2[r] = a.z;
      qcode[r] = __float_as_int(a.w);
      qch[r]   = qcode[r] >> 16;
      qd0[r] = dq.x; qd1[r] = dq.y; qd2[r] = dq.z; qq[r] = dq.w;
    }
    float l[4], a0[4], a1[4], a2[4];
    #pragma unroll
    for (int r = 0; r < 4; r++) { l[r]=0.f; a0[r]=0.f; a1[r]=0.f; a2[r]=0.f; }

    #pragma unroll 4
    for (int ki = 0; ki < 16; ki++) {
      const int kk = ki*32 + lane;
      float4 ka = sKA[kk];
      float4 kb = sKB[kk];
      float4 kv = sKV[kk];
      int kcode  = __float_as_int(ka.w);
      int kchain = kcode >> 16;
      #pragma unroll
      for (int r = 0; r < 4; r++) {
        float rt = qr0[r]*ka.x + qr1[r]*ka.y + qr2[r]*ka.z;
        float d2 = __fmaf_rn(qd0[r], kb.x,
                   __fmaf_rn(qd1[r], kb.y,
                   __fmaf_rn(qd2[r], kb.z, kb.w)));
        d2 = fmaxf(d2 + qq[r], 0.f);
        float bias = (kcode == qcode[r]) ? INVLN2
                   : (kchain == qch[r] ? 0.0f : -1e30f);
        float sc = rt - fast_sqrt(d2) + bias;
        float p = fast_ex2(sc);
        l[r]  += p;
        a0[r] += p*kv.x; a1[r] += p*kv.y; a2[r] += p*kv.z;
      }
    }
    #pragma unroll
    for (int r = 0; r < 4; r++) {
      float L  = warp_sum(l[r]);
      float A0 = warp_sum(a0[r]);
      float A1 = warp_sum(a1[r]);
      float A2 = warp_sum(a2[r]);
      if (lane == r)
        PART[base + q0 + r] = make_float4(L, A0, A1, A2);
    }
  }
}

// ---------------------------------------------------------------------------
// k3: fused partial-merge + back-rotation + mask + output GEMM.
// ---------------------------------------------------------------------------
__global__ __launch_bounds__(256) void k3_out(
    const float* __restrict__ rot, const int* __restrict__ amask,
    const float* __restrict__ w_out, float* __restrict__ out)
{
  __shared__ float w_s[48*64];    // [d][c]
  __shared__ float a_s[48*128];   // [d][r]
  __shared__ float rot_s[128*9];
  const int tid = threadIdx.x;
  const int ct = blockIdx.x & 15, st = blockIdx.x >> 4;
  const int cb = ct*64, sb = st*128;

  for (int idx = tid; idx < 64*48; idx += 256) {
    int c = idx/48, d = idx - c*48;
    w_s[d*64 + c] = w_out[(size_t)(cb + c)*48 + d];
  }
  for (int idx = tid; idx < 128*9; idx += 256)
    rot_s[idx] = rot[(size_t)sb*9 + idx];
  __syncthreads();

  // merge k-half partials -> normalize -> back-rotate -> mask -> a_s
  for (int i = tid; i < 128*16; i += 256) {
    int r = i & 127, h = i >> 7;
    int row = sb + r;
    int b = row >> 10, q = row & 1023;
    int idx = ((b*HH + h) << 10) + q;
    float4 p0 = g_part0[idx];
    float4 p1 = g_part1[idx];
    float inv = 1.f / (p0.x + p1.x);
    float o0 = (p0.y + p1.y) * inv;
    float o1 = (p0.z + p1.z) * inv;
    float o2 = (p0.w + p1.w) * inv;
    const float* R = &rot_s[r*9];
    float mk = (amask[row] != 0) ? 1.f : 0.f;
    a_s[(h*3+0)*128 + r] = (R[0]*o0 + R[3]*o1 + R[6]*o2) * mk;
    a_s[(h*3+1)*128 + r] = (R[1]*o0 + R[4]*o1 + R[7]*o2) * mk;
    a_s[(h*3+2)*128 + r] = (R[2]*o0 + R[5]*o1 + R[8]*o2) * mk;
  }
  __syncthreads();

  const int tx = tid & 15, ty = tid >> 4;
  float acc[8][4];
  #pragma unroll
  for (int i = 0; i < 8; i++)
    #pragma unroll
    for (int j = 0; j < 4; j++) acc[i][j] = 0.f;

  #pragma unroll 4
  for (int d = 0; d < 48; d++) {
    float4 wv = *(const float4*)&w_s[d*64 + tx*4];
    float4 aA = *(const float4*)&a_s[d*128 + ty*8];
    float4 aB = *(const float4*)&a_s[d*128 + ty*8 + 4];
    float av[8] = {aA.x, aA.y, aA.z, aA.w, aB.x, aB.y, aB.z, aB.w};
    #pragma unroll
    for (int i = 0; i < 8; i++) {
      acc[i][0] += av[i]*wv.x;
      acc[i][1] += av[i]*wv.y;
      acc[i][2] += av[i]*wv.z;
      acc[i][3] += av[i]*wv.w;
    }
  }
  #pragma unroll
  for (int i = 0; i < 8; i++) {
    float4 res = make_float4(acc[i][0], acc[i][1], acc[i][2], acc[i][3]);
    *(float4*)&out[(size_t)(sb + ty*8 + i)*1024 + cb + tx*4] = res;
  }
}

// ---------------------------------------------------------------------------
extern "C" void kernel_launch(void* const* d_in, const int* in_sizes, int n_in,
                              void* d_out, int out_size)
{
  const float* s          = (const float*)d_in[0];
  const float* rot        = (const float*)d_in[1];
  const float* trans      = (const float*)d_in[2];
  const float* ln_w       = (const float*)d_in[3];
  const float* w_proj     = (const float*)d_in[4];
  const float* w_out      = (const float*)d_in[5];
  const float* dist_scale = (const float*)d_in[6];
  const float* rot_scale  = (const float*)d_in[7];
  const int* am           = (const int*)d_in[8];
  const int* seq_id       = (const int*)d_in[9];
  const int* chain_id     = (const int*)d_in[10];
  float* out = (float*)d_out;

  k1a_stats  <<<256, 256>>>(s, w_proj);
  k1b_gemm   <<<dim3(4,32), 256>>>(s, ln_w);
  k1c_scatter<<<128, 256>>>(rot, trans, dist_scale, rot_scale, am, seq_id, chain_id);
  k2a_attn   <<<1024, 128>>>();
  k3_out     <<<256, 256>>>(rot, am, w_out, out);
}